// round 13
// baseline (speedup 1.0000x reference)
#include <cuda_runtime.h>
#include <cuda_fp16.h>
#include <cstdint>

// ---------------- problem constants ----------------
#define MM   8192
#define NN   2048
#define KIN  2048
#define KK   4096
#define NELEM_GRID ((double)KIN*NN*8)

// ---------------- GEMM tiling (fp16 operands, fp32 accum) -----------------
// Barrier-free mainloop: A via PER-WARP private cp.async stages,
// B via direct fragment LDG from L1/L2. No __syncthreads in the loop.
#define BM 128
#define BN 128
#define KTILE 32              // K halves per A stage
#define ASTR 40               // padded row stride in halves (80 B) - conflict-free
#define NSTAGE 4
#define NT (KK / KTILE)       // 128

#define WBYTES (32 * ASTR * 2)               // 2560 B per warp per stage
#define WOFF(w, s) (((w) * NSTAGE + (s)) * WBYTES)
#define SMEM_TOTAL (8 * NSTAGE * WBYTES)     // 81920 -> 2 CTAs/SM

// B fragment-major layout: slot(S, J, l) = uint2 (8 bytes)
//   S = k16-slice (0..255), J = n8-tile (0..255), l = lane (0..31)
#define NSLICE 256
#define NJ     256
__device__ uint2 g_Bf[(size_t)(NSLICE + 1) * NJ * 32];  // +1 slice tail pad
__device__ __half g_A[(size_t)MM * KK];    // [M][K]: [x | basis]
__device__ unsigned long long g_meanacc;   // fixed-point (2^-32) grid sum

// ---------------- helpers ----------------
__device__ __forceinline__ void cp16ca(uint32_t smem, const void* gmem) {
    asm volatile("cp.async.ca.shared.global [%0], [%1], 16;" :: "r"(smem), "l"(gmem));
}

__device__ __forceinline__ void ldsm4(uint32_t* r, uint32_t addr) {
    asm volatile("ldmatrix.sync.aligned.m8n8.x4.shared.b16 {%0,%1,%2,%3}, [%4];"
                 : "=r"(r[0]), "=r"(r[1]), "=r"(r[2]), "=r"(r[3]) : "r"(addr));
}

__device__ __forceinline__ void mma_f16(float* d, const uint32_t* a, uint32_t b0, uint32_t b1) {
    asm volatile(
        "mma.sync.aligned.m16n8k16.row.col.f32.f16.f16.f32 "
        "{%0,%1,%2,%3}, {%4,%5,%6,%7}, {%8,%9}, {%0,%1,%2,%3};"
        : "+f"(d[0]), "+f"(d[1]), "+f"(d[2]), "+f"(d[3])
        : "r"(a[0]), "r"(a[1]), "r"(a[2]), "r"(a[3]), "r"(b0), "r"(b1));
}

__device__ __forceinline__ uint32_t pack_h2(float lo, float hi) {
    __half2 h = __floats2half2_rn(lo, hi);
    return *reinterpret_cast<uint32_t*>(&h);
}

// ======================= prep 1: grid reduce -> W2 fragments + mean =======
__global__ void k_gridsum(const float* __restrict__ grid) {
    __shared__ float tile[32][33];
    __shared__ float red[256];
    int i0 = blockIdx.x * 32, o0 = blockIdx.y * 32;
    int tx = threadIdx.x & 31, ty = threadIdx.x >> 5;   // 32 x 8
    const float4* g4 = reinterpret_cast<const float4*>(grid);
    float loc = 0.f;
    #pragma unroll
    for (int r = ty; r < 32; r += 8) {
        size_t idx8 = (size_t)(i0 + r) * NN + (o0 + tx);
        float4 p = g4[idx8 * 2];
        float4 q = g4[idx8 * 2 + 1];
        float s = ((p.x + p.y) + (p.z + p.w)) + ((q.x + q.y) + (q.z + q.w));
        tile[r][tx] = s;   // tile[i_local][o_local]
        loc += s;
    }
    red[threadIdx.x] = loc;
    __syncthreads();

    // write phase: 256 threads cover 2 S x 4 J x 32 lanes = 256 slots
    {
        int t  = threadIdx.x;
        int sS = t >> 7;            // 0..1
        int sJ = (t >> 5) & 3;      // 0..3
        int l  = t & 31;            // lane
        int o_loc = sJ * 8 + (l >> 2);
        int i_loc = sS * 16 + (l & 3) * 2;
        uint2 u;
        u.x = pack_h2(tile[i_loc][o_loc],     tile[i_loc + 1][o_loc]);
        u.y = pack_h2(tile[i_loc + 8][o_loc], tile[i_loc + 9][o_loc]);
        int S = 128 + (i0 >> 4) + sS;
        int J = (o0 >> 3) + sJ;
        g_Bf[((size_t)S * NJ + J) * 32 + l] = u;
    }

    for (int off = 128; off > 0; off >>= 1) {
        if (threadIdx.x < off) red[threadIdx.x] += red[threadIdx.x + off];
        __syncthreads();
    }
    if (threadIdx.x == 0) {
        long long q = llrint((double)red[0] * 4294967296.0);
        atomicAdd(&g_meanacc, (unsigned long long)q);
    }
}

// ======================= prep 2: Wb -> fragment slots (S in [0,128)) ======
__global__ void k_packWb(const float* __restrict__ bw) {
    int t = blockIdx.x * 256 + threadIdx.x;  // one slot per thread, 1M total
    int S = t >> 13;            // 0..127
    int J = (t >> 5) & 255;     // 0..255
    int l = t & 31;             // lane
    int n  = J * 8 + (l >> 2);
    int k0 = S * 16 + (l & 3) * 2;
    const float2* bw2 = reinterpret_cast<const float2*>(bw);
    float2 a = bw2[(size_t)n * (KIN / 2) + (k0 >> 1)];
    float2 b = bw2[(size_t)n * (KIN / 2) + (k0 >> 1) + 4];
    uint2 u;
    u.x = pack_h2(a.x, a.y);
    u.y = pack_h2(b.x, b.y);
    g_Bf[((size_t)S * NJ + J) * 32 + l] = u;
}

// ======================= prep 3: build A = [x | basis] (half) =============
__global__ void k_buildA(const float* __restrict__ x) {
    int t = blockIdx.x * 256 + threadIdx.x;
    int b = t >> 9, c4 = t & 511;
    const float4* x4 = reinterpret_cast<const float4*>(x);
    float4 v = x4[(size_t)b * 512 + c4];
    double acc = (double)(long long)g_meanacc;
    float m = (float)(acc * (1.0 / 4294967296.0) / NELEM_GRID);
    __half2* A2 = reinterpret_cast<__half2*>(g_A);
    size_t base = (size_t)b * (KK / 2) + c4 * 2;
    A2[base + 0] = __floats2half2_rn(v.x, v.y);
    A2[base + 1] = __floats2half2_rn(v.z, v.w);
    float dx = v.x - m, dy = v.y - m, dz = v.z - m, dw = v.w - m;
    size_t base2 = base + (KIN / 2);
    A2[base2 + 0] = __floats2half2_rn(__expf(-dx * dx), __expf(-dy * dy));
    A2[base2 + 1] = __floats2half2_rn(__expf(-dz * dz), __expf(-dw * dw));
}

// == main GEMM: 128x128x32, barrier-free: per-warp A stages + B frag LDG ===
__global__ __launch_bounds__(256, 2) void k_gemm(float* __restrict__ out) {
    extern __shared__ char smc[];
    uint32_t sb = (uint32_t)__cvta_generic_to_shared(smc);

    // reset mean accumulator for the next graph replay
    if (blockIdx.x == 0 && blockIdx.y == 0 && threadIdx.x == 0) g_meanacc = 0ULL;

    int tid  = threadIdx.x;
    int warp = tid >> 5, lane = tid & 31;
    int wm = warp & 3;         // 4 warps along M -> 32 rows each
    int wn = warp >> 2;        // 2 warps along N -> 64 cols each
    int g  = lane >> 2;        // 0..7
    int tg = lane & 3;         // 0..3
    int m0 = blockIdx.y * BM;
    int n0 = blockIdx.x * BN;

    // --- per-warp A staging: lane covers 4 chunks: row = i*8 + lane/4, col16 = lane%4
    int arow = lane >> 2;              // base row 0..7 (+ i*8)
    int acol = lane & 3;               // 16B column 0..3
    const __half* Agw = g_A + (size_t)(m0 + wm * 32 + arow) * KK + acol * 8;
    uint32_t dW = (uint32_t)(arow * (ASTR * 2) + acol * 16);
    uint32_t wbase = sb + WOFF(warp, 0);
    // row stride for i: 8 rows -> global 8*KK halves, smem 8*ASTR*2 bytes

    // --- A ldmatrix lane offsets within own warp stage (rows 0..31 local) --
    uint32_t a_lane = (uint32_t)((lane & 15) * (ASTR * 2) + (lane >> 4) * 16);

    // --- B fragment base: warp covers J = (n0/8) + wn*8 + f, f in 0..7 -----
    const uint2* Bp = g_Bf + ((size_t)((n0 >> 3) + wn * 8)) * 32 + lane;

    float acc[2][8][4];
    #pragma unroll
    for (int i = 0; i < 2; i++)
        #pragma unroll
        for (int j = 0; j < 8; j++)
            #pragma unroll
            for (int k = 0; k < 4; k++) acc[i][j][k] = 0.f;

    // A prologue: stages 0..2 (per-warp, no block sync ever)
    #pragma unroll
    for (int s = 0; s < NSTAGE - 1; ++s) {
        int k0 = s * KTILE;
        #pragma unroll
        for (int i = 0; i < 4; ++i)
            cp16ca(wbase + s * WBYTES + dW + i * (8 * ASTR * 2),
                   Agw + (size_t)i * 8 * KK + k0);
        asm volatile("cp.async.commit_group;");
    }

    // B prologue: slice 0 -> breg[0]
    uint2 breg[2][8];
    #pragma unroll
    for (int f = 0; f < 8; ++f)
        breg[0][f] = __ldg(Bp + f * 32);

    #pragma unroll 1
    for (int kt = 0; kt < NT; ++kt) {
        asm volatile("cp.async.wait_group %0;" :: "n"(NSTAGE - 2));
        __syncwarp();

        if (kt + NSTAGE - 1 < NT) {
            int s  = (kt + NSTAGE - 1) & (NSTAGE - 1);
            int k0 = (kt + NSTAGE - 1) * KTILE;
            #pragma unroll
            for (int i = 0; i < 4; ++i)
                cp16ca(wbase + s * WBYTES + dW + i * (8 * ASTR * 2),
                       Agw + (size_t)i * 8 * KK + k0);
        }
        asm volatile("cp.async.commit_group;");

        uint32_t abase = wbase + (kt & (NSTAGE - 1)) * WBYTES + a_lane;

        #pragma unroll
        for (int s = 0; s < 2; ++s) {                 // two k16 slices; parity == s
            int Snext = kt * 2 + s + 1;               // next global slice (padded tail)
            #pragma unroll
            for (int f = 0; f < 8; ++f)
                breg[s ^ 1][f] = __ldg(Bp + (size_t)Snext * (NJ * 32) + f * 32);

            uint32_t af[2][4];
            ldsm4(af[0], abase + s * 32);
            ldsm4(af[1], abase + s * 32 + 16 * (ASTR * 2));

            #pragma unroll
            for (int f = 0; f < 8; ++f) {
                uint2 bb = breg[s][f];
                #pragma unroll
                for (int mf = 0; mf < 2; ++mf)
                    mma_f16(acc[mf][f], af[mf], bb.x, bb.y);
            }
        }
        __syncwarp();
    }

    // epilogue (no sync needed: each warp owns its output tile)
    #pragma unroll
    for (int mf = 0; mf < 2; ++mf) {
        #pragma unroll
        for (int nf = 0; nf < 8; ++nf) {
            int row0 = m0 + wm * 32 + mf * 16 + g;
            int col  = n0 + wn * 64 + nf * 8 + tg * 2;
            float2 v0 = make_float2(acc[mf][nf][0], acc[mf][nf][1]);
            float2 v1 = make_float2(acc[mf][nf][2], acc[mf][nf][3]);
            *reinterpret_cast<float2*>(&out[(size_t)row0 * NN + col])       = v0;
            *reinterpret_cast<float2*>(&out[(size_t)(row0 + 8) * NN + col]) = v1;
        }
    }
}

// ============================= launch =====================================
extern "C" void kernel_launch(void* const* d_in, const int* in_sizes, int n_in,
                              void* d_out, int out_size) {
    const float* x    = (const float*)d_in[0];   // (8192, 2048)
    const float* bw   = (const float*)d_in[1];   // (2048, 2048)
    const float* grid = (const float*)d_in[2];   // (2048, 2048, 8)
    float* out = (float*)d_out;                  // (8192, 2048)

    cudaFuncSetAttribute(k_gemm, cudaFuncAttributeMaxDynamicSharedMemorySize, SMEM_TOTAL);

    k_gridsum<<<dim3(KIN / 32, NN / 32), 256>>>(grid);
    k_packWb<<<(128 * 256 * 32) / 256, 256>>>(bw);
    k_buildA<<<(MM * KIN / 4) / 256, 256>>>(x);
    k_gemm<<<dim3(NN / BN, MM / BM), 256, SMEM_TOTAL>>>(out);
}

// round 14
// speedup vs baseline: 1.2557x; 1.2557x over previous
#include <cuda_runtime.h>
#include <cuda_fp16.h>
#include <cstdint>

// ---------------- problem constants ----------------
#define MM   8192
#define NN   2048
#define KIN  2048
#define KK   4096
#define NELEM_GRID ((double)KIN*NN*8)

// ---------------- GEMM: fully smem-free, fragment-direct ------------------
// A and B both pre-packed in mma.sync fragment-major layout; the GEMM loads
// fragments straight from L1/L2 with __ldg and never touches shared memory.
#define BM 128
#define BN 128
#define NSLICE 256            // k16 slices
#define NI     512            // m16 tiles
#define NJ     256            // n8 tiles

// A fragment slots: (S, I, lane) -> uint4  (a0,a1,a2,a3)
__device__ uint4 g_Af[(size_t)(NSLICE + 1) * NI * 32];   // +1 slice tail pad
// B fragment slots: (S, J, lane) -> uint2  (b0,b1)
__device__ uint2 g_Bf[(size_t)(NSLICE + 1) * NJ * 32];   // +1 slice tail pad
__device__ unsigned long long g_meanacc;   // fixed-point (2^-32) grid sum

// ---------------- helpers ----------------
__device__ __forceinline__ void mma_f16(float* d, const uint4& a, uint32_t b0, uint32_t b1) {
    asm volatile(
        "mma.sync.aligned.m16n8k16.row.col.f32.f16.f16.f32 "
        "{%0,%1,%2,%3}, {%4,%5,%6,%7}, {%8,%9}, {%0,%1,%2,%3};"
        : "+f"(d[0]), "+f"(d[1]), "+f"(d[2]), "+f"(d[3])
        : "r"(a.x), "r"(a.y), "r"(a.z), "r"(a.w), "r"(b0), "r"(b1));
}

__device__ __forceinline__ uint32_t pack_h2(float lo, float hi) {
    __half2 h = __floats2half2_rn(lo, hi);
    return *reinterpret_cast<uint32_t*>(&h);
}

// ======================= prep 1: grid reduce -> W2 B-fragments + mean =====
__global__ void k_gridsum(const float* __restrict__ grid) {
    __shared__ float tile[32][33];
    __shared__ float red[256];
    int i0 = blockIdx.x * 32, o0 = blockIdx.y * 32;
    int tx = threadIdx.x & 31, ty = threadIdx.x >> 5;   // 32 x 8
    const float4* g4 = reinterpret_cast<const float4*>(grid);
    float loc = 0.f;
    #pragma unroll
    for (int r = ty; r < 32; r += 8) {
        size_t idx8 = (size_t)(i0 + r) * NN + (o0 + tx);
        float4 p = g4[idx8 * 2];
        float4 q = g4[idx8 * 2 + 1];
        float s = ((p.x + p.y) + (p.z + p.w)) + ((q.x + q.y) + (q.z + q.w));
        tile[r][tx] = s;   // tile[i_local][o_local]
        loc += s;
    }
    red[threadIdx.x] = loc;
    __syncthreads();

    // write phase: 256 threads cover 2 S x 4 J x 32 lanes = 256 slots
    {
        int t  = threadIdx.x;
        int sS = t >> 7;            // 0..1
        int sJ = (t >> 5) & 3;      // 0..3
        int l  = t & 31;            // lane
        int o_loc = sJ * 8 + (l >> 2);
        int i_loc = sS * 16 + (l & 3) * 2;
        uint2 u;
        u.x = pack_h2(tile[i_loc][o_loc],     tile[i_loc + 1][o_loc]);
        u.y = pack_h2(tile[i_loc + 8][o_loc], tile[i_loc + 9][o_loc]);
        int S = 128 + (i0 >> 4) + sS;
        int J = (o0 >> 3) + sJ;
        g_Bf[((size_t)S * NJ + J) * 32 + l] = u;
    }

    for (int off = 128; off > 0; off >>= 1) {
        if (threadIdx.x < off) red[threadIdx.x] += red[threadIdx.x + off];
        __syncthreads();
    }
    if (threadIdx.x == 0) {
        long long q = llrint((double)red[0] * 4294967296.0);
        atomicAdd(&g_meanacc, (unsigned long long)q);
    }
}

// ======================= prep 2: Wb -> B-fragment slots (S in [0,128)) ====
__global__ void k_packWb(const float* __restrict__ bw) {
    int t = blockIdx.x * 256 + threadIdx.x;  // one slot per thread, 1M total
    int S = t >> 13;            // 0..127
    int J = (t >> 5) & 255;     // 0..255
    int l = t & 31;             // lane
    int n  = J * 8 + (l >> 2);
    int k0 = S * 16 + (l & 3) * 2;
    const float2* bw2 = reinterpret_cast<const float2*>(bw);
    float2 a = bw2[(size_t)n * (KIN / 2) + (k0 >> 1)];
    float2 b = bw2[(size_t)n * (KIN / 2) + (k0 >> 1) + 4];
    uint2 u;
    u.x = pack_h2(a.x, a.y);
    u.y = pack_h2(b.x, b.y);
    g_Bf[((size_t)S * NJ + J) * 32 + l] = u;
}

// ======= prep 3: x -> A-fragment slots [x half: S<128, basis: S>=128] =====
// One thread builds BOTH the x-slot (S) and the basis-slot (S+128) from the
// same 4 float2 loads.  2M threads total.
__global__ void k_buildA(const float* __restrict__ x) {
    int t = blockIdx.x * 256 + threadIdx.x;
    int l  = t & 31;             // lane
    int I  = (t >> 5) & 511;     // m16 tile
    int S  = t >> 14;            // 0..127 (k16 slice within x half)
    int m  = I * 16 + (l >> 2);
    int k0 = S * 16 + (l & 3) * 2;
    const float2* x2 = reinterpret_cast<const float2*>(x);
    float2 f0 = x2[(size_t)m * (KIN / 2) + (k0 >> 1)];           // (m,   k0..k0+1)
    float2 f1 = x2[(size_t)(m + 8) * (KIN / 2) + (k0 >> 1)];     // (m+8, k0..k0+1)
    float2 f2 = x2[(size_t)m * (KIN / 2) + (k0 >> 1) + 4];       // (m,   k0+8..9)
    float2 f3 = x2[(size_t)(m + 8) * (KIN / 2) + (k0 >> 1) + 4]; // (m+8, k0+8..9)

    uint4 ux;
    ux.x = pack_h2(f0.x, f0.y);
    ux.y = pack_h2(f1.x, f1.y);
    ux.z = pack_h2(f2.x, f2.y);
    ux.w = pack_h2(f3.x, f3.y);
    g_Af[((size_t)S * NI + I) * 32 + l] = ux;

    double acc = (double)(long long)g_meanacc;
    float mn = (float)(acc * (1.0 / 4294967296.0) / NELEM_GRID);
    float d0 = f0.x - mn, d1 = f0.y - mn, d2 = f1.x - mn, d3 = f1.y - mn;
    float d4 = f2.x - mn, d5 = f2.y - mn, d6 = f3.x - mn, d7 = f3.y - mn;
    uint4 ub;
    ub.x = pack_h2(__expf(-d0 * d0), __expf(-d1 * d1));
    ub.y = pack_h2(__expf(-d2 * d2), __expf(-d3 * d3));
    ub.z = pack_h2(__expf(-d4 * d4), __expf(-d5 * d5));
    ub.w = pack_h2(__expf(-d6 * d6), __expf(-d7 * d7));
    g_Af[((size_t)(S + 128) * NI + I) * 32 + l] = ub;
}

// ========== main GEMM: smem-free, fragment-direct, barrier-free ===========
__global__ __launch_bounds__(256, 2) void k_gemm(float* __restrict__ out) {
    // reset mean accumulator for the next graph replay
    if (blockIdx.x == 0 && blockIdx.y == 0 && threadIdx.x == 0) g_meanacc = 0ULL;

    int tid  = threadIdx.x;
    int warp = tid >> 5, lane = tid & 31;
    int wm = warp & 3;         // 4 warps along M -> 32 rows each
    int wn = warp >> 2;        // 2 warps along N -> 64 cols each
    int g  = lane >> 2;        // 0..7
    int tg = lane & 3;         // 0..3
    int m0 = blockIdx.y * BM;
    int n0 = blockIdx.x * BN;

    // fragment base pointers
    // A: warp covers I = (m0/16) + wm*2 + mf, mf in 0..1
    const uint4* Ap = g_Af + ((size_t)((m0 >> 4) + wm * 2)) * 32 + lane;
    // B: warp covers J = (n0/8) + wn*8 + f, f in 0..7
    const uint2* Bp = g_Bf + ((size_t)((n0 >> 3) + wn * 8)) * 32 + lane;

    float acc[2][8][4];
    #pragma unroll
    for (int i = 0; i < 2; i++)
        #pragma unroll
        for (int j = 0; j < 8; j++)
            #pragma unroll
            for (int k = 0; k < 4; k++) acc[i][j][k] = 0.f;

    // prologue: slice 0 fragments
    uint4 areg[2][2];
    uint2 breg[2][8];
    #pragma unroll
    for (int mf = 0; mf < 2; ++mf)
        areg[0][mf] = __ldg(Ap + mf * 32);
    #pragma unroll
    for (int f = 0; f < 8; ++f)
        breg[0][f] = __ldg(Bp + f * 32);

    #pragma unroll 4
    for (int S = 0; S < NSLICE; ++S) {
        int par = S & 1;
        // prefetch next slice (tail lands in the pad slice)
        size_t offA = (size_t)(S + 1) * (NI * 32);
        size_t offB = (size_t)(S + 1) * (NJ * 32);
        #pragma unroll
        for (int mf = 0; mf < 2; ++mf)
            areg[par ^ 1][mf] = __ldg(Ap + offA + mf * 32);
        #pragma unroll
        for (int f = 0; f < 8; ++f)
            breg[par ^ 1][f] = __ldg(Bp + offB + f * 32);

        #pragma unroll
        for (int f = 0; f < 8; ++f) {
            uint2 bb = breg[par][f];
            #pragma unroll
            for (int mf = 0; mf < 2; ++mf)
                mma_f16(acc[mf][f], areg[par][mf], bb.x, bb.y);
        }
    }

    // epilogue (warp-private output tile, no sync needed)
    #pragma unroll
    for (int mf = 0; mf < 2; ++mf) {
        #pragma unroll
        for (int nf = 0; nf < 8; ++nf) {
            int row0 = m0 + wm * 32 + mf * 16 + g;
            int col  = n0 + wn * 64 + nf * 8 + tg * 2;
            float2 v0 = make_float2(acc[mf][nf][0], acc[mf][nf][1]);
            float2 v1 = make_float2(acc[mf][nf][2], acc[mf][nf][3]);
            *reinterpret_cast<float2*>(&out[(size_t)row0 * NN + col])       = v0;
            *reinterpret_cast<float2*>(&out[(size_t)(row0 + 8) * NN + col]) = v1;
        }
    }
}

// ============================= launch =====================================
extern "C" void kernel_launch(void* const* d_in, const int* in_sizes, int n_in,
                              void* d_out, int out_size) {
    const float* x    = (const float*)d_in[0];   // (8192, 2048)
    const float* bw   = (const float*)d_in[1];   // (2048, 2048)
    const float* grid = (const float*)d_in[2];   // (2048, 2048, 8)
    float* out = (float*)d_out;                  // (8192, 2048)

    k_gridsum<<<dim3(KIN / 32, NN / 32), 256>>>(grid);
    k_packWb<<<(128 * 256 * 32) / 256, 256>>>(bw);
    k_buildA<<<(128 * 512 * 32) / 256, 256>>>(x);
    k_gemm<<<dim3(NN / BN, MM / BM), 256>>>(out);
}

// round 15
// speedup vs baseline: 1.2776x; 1.0174x over previous
#include <cuda_runtime.h>
#include <cuda_fp16.h>
#include <cstdint>

// ---------------- problem constants ----------------
#define MM   8192
#define NN   2048
#define KIN  2048
#define KK   4096
#define NELEM_GRID ((double)KIN*NN*8)

// ---------------- GEMM: smem-free fragment-direct, persistent CTAs --------
#define BM 128
#define BN 128
#define NSLICE 256            // k16 slices
#define NI     512            // m16 tiles
#define NJ     256            // n8 tiles
#define NTILE  1024           // (MM/BM) * (NN/BN)
#define PGRID  304            // persistent grid (2 CTAs x 152 SMs)
#define PFD    8              // L2 prefetch distance (slices)

// A fragment slots: (S, I, lane) -> uint4  (a0,a1,a2,a3)
__device__ uint4 g_Af[(size_t)(NSLICE + 1) * NI * 32];   // +1 slice tail pad
// B fragment slots: (S, J, lane) -> uint2  (b0,b1)
__device__ uint2 g_Bf[(size_t)(NSLICE + 1) * NJ * 32];   // +1 slice tail pad
__device__ unsigned long long g_meanacc;   // fixed-point (2^-32) grid sum
__device__ unsigned int g_tile;            // persistent tile counter

// ---------------- helpers ----------------
__device__ __forceinline__ void mma_f16(float* d, const uint4& a, uint32_t b0, uint32_t b1) {
    asm volatile(
        "mma.sync.aligned.m16n8k16.row.col.f32.f16.f16.f32 "
        "{%0,%1,%2,%3}, {%4,%5,%6,%7}, {%8,%9}, {%0,%1,%2,%3};"
        : "+f"(d[0]), "+f"(d[1]), "+f"(d[2]), "+f"(d[3])
        : "r"(a.x), "r"(a.y), "r"(a.z), "r"(a.w), "r"(b0), "r"(b1));
}

__device__ __forceinline__ uint32_t pack_h2(float lo, float hi) {
    __half2 h = __floats2half2_rn(lo, hi);
    return *reinterpret_cast<uint32_t*>(&h);
}

__device__ __forceinline__ void pf_l2(const void* p) {
    asm volatile("prefetch.global.L2 [%0];" :: "l"(p));
}

// ======================= prep 1: grid reduce -> W2 B-fragments + mean =====
__global__ void k_gridsum(const float* __restrict__ grid) {
    __shared__ float tile[32][33];
    __shared__ float red[256];
    // reset persistent tile counter for the next k_gemm (stream-ordered)
    if (blockIdx.x == 0 && blockIdx.y == 0 && threadIdx.x == 0) g_tile = 0u;
    int i0 = blockIdx.x * 32, o0 = blockIdx.y * 32;
    int tx = threadIdx.x & 31, ty = threadIdx.x >> 5;   // 32 x 8
    const float4* g4 = reinterpret_cast<const float4*>(grid);
    float loc = 0.f;
    #pragma unroll
    for (int r = ty; r < 32; r += 8) {
        size_t idx8 = (size_t)(i0 + r) * NN + (o0 + tx);
        float4 p = g4[idx8 * 2];
        float4 q = g4[idx8 * 2 + 1];
        float s = ((p.x + p.y) + (p.z + p.w)) + ((q.x + q.y) + (q.z + q.w));
        tile[r][tx] = s;   // tile[i_local][o_local]
        loc += s;
    }
    red[threadIdx.x] = loc;
    __syncthreads();

    // write phase: 256 threads cover 2 S x 4 J x 32 lanes = 256 slots
    {
        int t  = threadIdx.x;
        int sS = t >> 7;            // 0..1
        int sJ = (t >> 5) & 3;      // 0..3
        int l  = t & 31;            // lane
        int o_loc = sJ * 8 + (l >> 2);
        int i_loc = sS * 16 + (l & 3) * 2;
        uint2 u;
        u.x = pack_h2(tile[i_loc][o_loc],     tile[i_loc + 1][o_loc]);
        u.y = pack_h2(tile[i_loc + 8][o_loc], tile[i_loc + 9][o_loc]);
        int S = 128 + (i0 >> 4) + sS;
        int J = (o0 >> 3) + sJ;
        g_Bf[((size_t)S * NJ + J) * 32 + l] = u;
    }

    for (int off = 128; off > 0; off >>= 1) {
        if (threadIdx.x < off) red[threadIdx.x] += red[threadIdx.x + off];
        __syncthreads();
    }
    if (threadIdx.x == 0) {
        long long q = llrint((double)red[0] * 4294967296.0);
        atomicAdd(&g_meanacc, (unsigned long long)q);
    }
}

// ======================= prep 2: Wb -> B-fragment slots (S in [0,128)) ====
__global__ void k_packWb(const float* __restrict__ bw) {
    int t = blockIdx.x * 256 + threadIdx.x;  // one slot per thread, 1M total
    int S = t >> 13;            // 0..127
    int J = (t >> 5) & 255;     // 0..255
    int l = t & 31;             // lane
    int n  = J * 8 + (l >> 2);
    int k0 = S * 16 + (l & 3) * 2;
    const float2* bw2 = reinterpret_cast<const float2*>(bw);
    float2 a = bw2[(size_t)n * (KIN / 2) + (k0 >> 1)];
    float2 b = bw2[(size_t)n * (KIN / 2) + (k0 >> 1) + 4];
    uint2 u;
    u.x = pack_h2(a.x, a.y);
    u.y = pack_h2(b.x, b.y);
    g_Bf[((size_t)S * NJ + J) * 32 + l] = u;
}

// ======= prep 3: x -> A-fragment slots [x half: S<128, basis: S>=128] =====
__global__ void k_buildA(const float* __restrict__ x) {
    int t = blockIdx.x * 256 + threadIdx.x;
    int l  = t & 31;             // lane
    int I  = (t >> 5) & 511;     // m16 tile
    int S  = t >> 14;            // 0..127 (k16 slice within x half)
    int m  = I * 16 + (l >> 2);
    int k0 = S * 16 + (l & 3) * 2;
    const float2* x2 = reinterpret_cast<const float2*>(x);
    float2 f0 = x2[(size_t)m * (KIN / 2) + (k0 >> 1)];
    float2 f1 = x2[(size_t)(m + 8) * (KIN / 2) + (k0 >> 1)];
    float2 f2 = x2[(size_t)m * (KIN / 2) + (k0 >> 1) + 4];
    float2 f3 = x2[(size_t)(m + 8) * (KIN / 2) + (k0 >> 1) + 4];

    uint4 ux;
    ux.x = pack_h2(f0.x, f0.y);
    ux.y = pack_h2(f1.x, f1.y);
    ux.z = pack_h2(f2.x, f2.y);
    ux.w = pack_h2(f3.x, f3.y);
    g_Af[((size_t)S * NI + I) * 32 + l] = ux;

    double acc = (double)(long long)g_meanacc;
    float mn = (float)(acc * (1.0 / 4294967296.0) / NELEM_GRID);
    float d0 = f0.x - mn, d1 = f0.y - mn, d2 = f1.x - mn, d3 = f1.y - mn;
    float d4 = f2.x - mn, d5 = f2.y - mn, d6 = f3.x - mn, d7 = f3.y - mn;
    uint4 ub;
    ub.x = pack_h2(__expf(-d0 * d0), __expf(-d1 * d1));
    ub.y = pack_h2(__expf(-d2 * d2), __expf(-d3 * d3));
    ub.z = pack_h2(__expf(-d4 * d4), __expf(-d5 * d5));
    ub.w = pack_h2(__expf(-d6 * d6), __expf(-d7 * d7));
    g_Af[((size_t)(S + 128) * NI + I) * 32 + l] = ub;
}

// == main GEMM: persistent, smem-free, fragment-direct, L2-prefetched ======
__global__ __launch_bounds__(256, 2) void k_gemm(float* __restrict__ out) {
    // reset mean accumulator for the next graph replay
    if (blockIdx.x == 0 && threadIdx.x == 0) g_meanacc = 0ULL;

    __shared__ unsigned int s_tile;
    int tid  = threadIdx.x;
    int warp = tid >> 5, lane = tid & 31;
    int wm = warp & 3;         // 4 warps along M -> 32 rows each
    int wn = warp >> 2;        // 2 warps along N -> 64 cols each
    int g  = lane >> 2;        // 0..7
    int tg = lane & 3;         // 0..3

    for (;;) {
        if (tid == 0) s_tile = atomicAdd(&g_tile, 1u);
        __syncthreads();
        unsigned int t = s_tile;
        __syncthreads();              // protect s_tile before next overwrite
        if (t >= NTILE) break;

        int n0 = (int)(t & 15) * BN;
        int m0 = (int)(t >> 4) * BM;

        const uint4* Ap = g_Af + ((size_t)((m0 >> 4) + wm * 2)) * 32 + lane;
        const uint2* Bp = g_Bf + ((size_t)((n0 >> 3) + wn * 8)) * 32 + lane;

        float acc[2][8][4];
        #pragma unroll
        for (int i = 0; i < 2; i++)
            #pragma unroll
            for (int j = 0; j < 8; j++)
                #pragma unroll
                for (int k = 0; k < 4; k++) acc[i][j][k] = 0.f;

        // prologue: slice 0 fragments
        uint4 areg[2][2];
        uint2 breg[2][8];
        #pragma unroll
        for (int mf = 0; mf < 2; ++mf)
            areg[0][mf] = __ldg(Ap + mf * 32);
        #pragma unroll
        for (int f = 0; f < 8; ++f)
            breg[0][f] = __ldg(Bp + f * 32);

        #pragma unroll 4
        for (int S = 0; S < NSLICE; ++S) {
            int par = S & 1;
            // L2 prefetch of A PFD slices ahead (clamped into the pad slice)
            int Spf = S + PFD; if (Spf > NSLICE) Spf = NSLICE;
            size_t offPF = (size_t)Spf * (NI * 32);
            pf_l2(Ap + offPF);
            pf_l2(Ap + offPF + 32);

            // prefetch next slice's fragments into registers
            size_t offA = (size_t)(S + 1) * (NI * 32);
            size_t offB = (size_t)(S + 1) * (NJ * 32);
            #pragma unroll
            for (int mf = 0; mf < 2; ++mf)
                areg[par ^ 1][mf] = __ldg(Ap + offA + mf * 32);
            #pragma unroll
            for (int f = 0; f < 8; ++f)
                breg[par ^ 1][f] = __ldg(Bp + offB + f * 32);

            #pragma unroll
            for (int f = 0; f < 8; ++f) {
                uint2 bb = breg[par][f];
                #pragma unroll
                for (int mf = 0; mf < 2; ++mf)
                    mma_f16(acc[mf][f], areg[par][mf], bb.x, bb.y);
            }
        }

        // epilogue (warp-private output tile)
        #pragma unroll
        for (int mf = 0; mf < 2; ++mf) {
            #pragma unroll
            for (int nf = 0; nf < 8; ++nf) {
                int row0 = m0 + wm * 32 + mf * 16 + g;
                int col  = n0 + wn * 64 + nf * 8 + tg * 2;
                float2 v0 = make_float2(acc[mf][nf][0], acc[mf][nf][1]);
                float2 v1 = make_float2(acc[mf][nf][2], acc[mf][nf][3]);
                *reinterpret_cast<float2*>(&out[(size_t)row0 * NN + col])       = v0;
                *reinterpret_cast<float2*>(&out[(size_t)(row0 + 8) * NN + col]) = v1;
            }
        }
    }
}

// ============================= launch =====================================
extern "C" void kernel_launch(void* const* d_in, const int* in_sizes, int n_in,
                              void* d_out, int out_size) {
    const float* x    = (const float*)d_in[0];   // (8192, 2048)
    const float* bw   = (const float*)d_in[1];   // (2048, 2048)
    const float* grid = (const float*)d_in[2];   // (2048, 2048, 8)
    float* out = (float*)d_out;                  // (8192, 2048)

    k_gridsum<<<dim3(KIN / 32, NN / 32), 256>>>(grid);
    k_packWb<<<(128 * 256 * 32) / 256, 256>>>(bw);
    k_buildA<<<(128 * 512 * 32) / 256, 256>>>(x);
    k_gemm<<<PGRID, 256>>>(out);
}